// round 4
// baseline (speedup 1.0000x reference)
#include <cuda_runtime.h>
#include <cuda_bf16.h>
#include <math.h>
#include <stdint.h>

#define B 32
#define NTOK 4096
#define DF 768
#define KS 8
#define DS 256
#define DH 256
#define NITER 3
#define EPSV 1e-8f
#define LNEPS 1e-5f
#define ATT_SCALE 0.0625f   // 256^-0.5

// ---------------- scratch (device globals; no allocation allowed) ----------
__device__ __align__(16) float d_stats[B * NTOK * 2];
__device__ __align__(16) float d_kf[(long)B * NTOK * DH];       // 134 MB
__device__ __align__(16) float d_vf[(long)B * NTOK * DS];       // 134 MB
__device__ __align__(16) __nv_bfloat16 d_Xh[(long)B * NTOK * DF];  // 201 MB
__device__ __align__(16) __nv_bfloat16 d_Xl[(long)B * NTOK * DF];  // 201 MB
__device__ __align__(16) __nv_bfloat16 d_Wh[(DH + DS) * DF];
__device__ __align__(16) __nv_bfloat16 d_Wl[(DH + DS) * DF];
__device__ __align__(16) float d_wgsum[DH + DS];
__device__ __align__(16) float d_wb[DH + DS];
__device__ __align__(16) float d_slots[B * KS * DS];
__device__ __align__(16) float d_q[B * KS * DH];
__device__ __align__(16) float d_U[B * KS * DS];
__device__ __align__(16) float d_S[B * KS];
__device__ __align__(16) float d_msum[B * KS];

// ================= mma.sync helpers (sm_80 baseline) ========================
__device__ __forceinline__ void ldsm4(uint32_t* r, uint32_t addr) {
    asm volatile("ldmatrix.sync.aligned.m8n8.x4.shared.b16 {%0,%1,%2,%3}, [%4];"
        : "=r"(r[0]), "=r"(r[1]), "=r"(r[2]), "=r"(r[3]) : "r"(addr));
}
__device__ __forceinline__ void mma16816(float* c, const uint32_t* a, const uint32_t* b) {
    asm volatile("mma.sync.aligned.m16n8k16.row.col.f32.bf16.bf16.f32 "
        "{%0,%1,%2,%3}, {%4,%5,%6,%7}, {%8,%9}, {%0,%1,%2,%3};"
        : "+f"(c[0]), "+f"(c[1]), "+f"(c[2]), "+f"(c[3])
        : "r"(a[0]), "r"(a[1]), "r"(a[2]), "r"(a[3]), "r"(b[0]), "r"(b[1]));
}
#define CPA(dst, src) asm volatile("cp.async.cg.shared.global [%0], [%1], 16;" :: "r"(dst), "l"(src))
#define CPC() asm volatile("cp.async.commit_group;" ::: "memory")
#define CPW1() asm volatile("cp.async.wait_group 1;" ::: "memory")
__device__ __forceinline__ uint32_t smem_u32(const void* p) {
    uint32_t a;
    asm("{ .reg .u64 t; cvta.to.shared.u64 t, %1; cvt.u32.u64 %0, t; }" : "=r"(a) : "l"(p));
    return a;
}

// ---------------- kernel 1: fold LN gain, build bf16 hi/lo weights ---------
__global__ void prep_weights(const float* __restrict__ Wk, const float* __restrict__ Wv,
                             const float* __restrict__ g_in, const float* __restrict__ b_in) {
    int j = blockIdx.x;            // 0..511
    int t = threadIdx.x;           // 256 threads
    const float* wrow = (j < DH) ? (Wk + (long)j * DF) : (Wv + (long)(j - DH) * DF);
    float sg = 0.f, sb = 0.f;
    for (int d = t; d < DF; d += 256) {
        float w = wrow[d];
        float g = g_in[d];
        float wg = w * g;
        __nv_bfloat16 hi = __float2bfloat16_rn(wg);
        d_Wh[(long)j * DF + d] = hi;
        d_Wl[(long)j * DF + d] = __float2bfloat16_rn(wg - __bfloat162float(hi));
        sg += wg;
        sb += w * b_in[d];
    }
    __shared__ float red[64];
#pragma unroll
    for (int o = 16; o; o >>= 1) {
        sg += __shfl_xor_sync(~0u, sg, o);
        sb += __shfl_xor_sync(~0u, sb, o);
    }
    int w = t >> 5, l = t & 31;
    if (l == 0) { red[w] = sg; red[32 + w] = sb; }
    __syncthreads();
    if (t == 0) {
        float a = 0.f, c = 0.f;
        for (int i = 0; i < 8; i++) { a += red[i]; c += red[32 + i]; }
        d_wgsum[j] = a;
        d_wb[j] = c;
    }
}

// ---------------- kernel 2: row stats + fp32 -> bf16 hi/lo conversion ------
__global__ void row_stats_cvt(const float* __restrict__ feat) {
    int w = threadIdx.x >> 5, l = threadIdx.x & 31;
    long row = (long)blockIdx.x * 8 + w;
    const float4* x = (const float4*)(feat + row * DF);
    float4 v[6];
    float s = 0.f, s2 = 0.f;
#pragma unroll
    for (int i = 0; i < 6; i++) {
        v[i] = x[l + 32 * i];
        s  += v[i].x + v[i].y + v[i].z + v[i].w;
        s2 += v[i].x * v[i].x + v[i].y * v[i].y + v[i].z * v[i].z + v[i].w * v[i].w;
    }
#pragma unroll
    for (int o = 16; o; o >>= 1) {
        s  += __shfl_xor_sync(~0u, s, o);
        s2 += __shfl_xor_sync(~0u, s2, o);
    }
    if (l == 0) {
        float m = s * (1.f / DF);
        float var = s2 * (1.f / DF) - m * m;
        d_stats[2 * row]     = m;
        d_stats[2 * row + 1] = rsqrtf(var + LNEPS);
    }
    // write bf16 hi/lo split of raw features
#pragma unroll
    for (int i = 0; i < 6; i++) {
        int col = 4 * l + 128 * i;
        const float* f = (const float*)&v[i];
        uint32_t H[2], L[2];
#pragma unroll
        for (int p = 0; p < 2; p++) {
            float a = f[2 * p], bv = f[2 * p + 1];
            __nv_bfloat162 hp, lp;
            hp.x = __float2bfloat16_rn(a); hp.y = __float2bfloat16_rn(bv);
            lp.x = __float2bfloat16_rn(a - __bfloat162float(hp.x));
            lp.y = __float2bfloat16_rn(bv - __bfloat162float(hp.y));
            H[p] = *(uint32_t*)&hp; L[p] = *(uint32_t*)&lp;
        }
        *(uint2*)(d_Xh + row * DF + col) = make_uint2(H[0], H[1]);
        *(uint2*)(d_Xl + row * DF + col) = make_uint2(L[0], L[1]);
    }
}

// ---------------- kernel 3: mma.sync bf16x3 fused LN + K/V GEMM ------------
// C(131072 x 512) = X @ Wg^T. CTA 64M x 128N, K-chunk 32, 3-stage cp.async,
// 2 CTAs/SM. Rows padded to 80B for conflict-free ldmatrix.
#define KCH 32
#define NCHUNKS 24
#define A_HI 0
#define A_LO 5120
#define B_HI 10240
#define B_LO 20480
#define STG  30720
#define SMEM_GEMM (3 * STG)

__global__ void __launch_bounds__(256, 2) kv_gemm_mma(void) {
    extern __shared__ char sm[];
    uint32_t sb = smem_u32(sm);
    int t = threadIdx.x;
    int w = t >> 5, l = t & 31;
    int wm = w & 1, wn = w >> 1;          // 2 m-warps x 4 n-warps
    int m0 = wm * 32, n0w = wn * 32;
    int N0 = blockIdx.x * 128;            // N fastest -> co-resident share X in L2
    long row0 = (long)blockIdx.y * 64;

    // producers
    int ar = t >> 2, aseg = t & 3;        // A: 64 rows x 4 segs
    const __nv_bfloat16* axh = d_Xh + (row0 + ar) * DF + aseg * 8;
    const __nv_bfloat16* axl = d_Xl + (row0 + ar) * DF + aseg * 8;
    uint32_t a_dh = sb + A_HI + ar * 80 + aseg * 16;
    uint32_t a_dl = sb + A_LO + ar * 80 + aseg * 16;
    int br = t >> 1, bs0 = (t & 1) * 2;   // B: 128 rows x 2 segs each
    const __nv_bfloat16* bwh = d_Wh + (size_t)(N0 + br) * DF + bs0 * 8;
    const __nv_bfloat16* bwl = d_Wl + (size_t)(N0 + br) * DF + bs0 * 8;
    uint32_t b_dh = sb + B_HI + br * 80 + bs0 * 16;
    uint32_t b_dl = sb + B_LO + br * 80 + bs0 * 16;

#define ISSUE(c, soff) { long ko_ = (long)(c) * KCH;            \
    CPA(a_dh + (soff), axh + ko_);                               \
    CPA(a_dl + (soff), axl + ko_);                               \
    CPA(b_dh + (soff), bwh + ko_);                               \
    CPA(b_dh + (soff) + 16, bwh + ko_ + 8);                      \
    CPA(b_dl + (soff), bwl + ko_);                               \
    CPA(b_dl + (soff) + 16, bwl + ko_ + 8); }

    // consumer ldmatrix bases
    uint32_t aA = sb + (uint32_t)(A_HI + (m0 + (l & 15)) * 80 + (l >> 4) * 16);
    uint32_t aB = sb + (uint32_t)(B_HI + (n0w + (l & 7) + ((l >> 4) & 1) * 8) * 80 + ((l >> 3) & 1) * 16);

    float acc[2][4][4];
#pragma unroll
    for (int i = 0; i < 2; i++)
#pragma unroll
        for (int j = 0; j < 4; j++)
#pragma unroll
            for (int q = 0; q < 4; q++) acc[i][j][q] = 0.f;

    ISSUE(0, 0); CPC();
    ISSUE(1, STG); CPC();

    for (int c = 0; c < NCHUNKS; c++) {
        uint32_t soff = (uint32_t)(c % 3) * STG;
        CPW1();
        __syncthreads();
        int cn = c + 2;
        if (cn < NCHUNKS) ISSUE(cn, (uint32_t)(cn % 3) * STG);
        CPC();
#pragma unroll
        for (int k16 = 0; k16 < 2; k16++) {
            uint32_t ah[2][4], al[2][4], bh[2][4], bl[2][4];
            ldsm4(ah[0], aA + soff + k16 * 32);
            ldsm4(ah[1], aA + soff + 16 * 80 + k16 * 32);
            ldsm4(al[0], aA + soff + (A_LO - A_HI) + k16 * 32);
            ldsm4(al[1], aA + soff + (A_LO - A_HI) + 16 * 80 + k16 * 32);
            ldsm4(bh[0], aB + soff + k16 * 32);
            ldsm4(bh[1], aB + soff + 16 * 80 + k16 * 32);
            ldsm4(bl[0], aB + soff + (B_LO - B_HI) + k16 * 32);
            ldsm4(bl[1], aB + soff + (B_LO - B_HI) + 16 * 80 + k16 * 32);
#pragma unroll
            for (int mt = 0; mt < 2; mt++)
#pragma unroll
                for (int g = 0; g < 2; g++) {
                    mma16816(acc[mt][2 * g],     ah[mt], &bh[g][0]);
                    mma16816(acc[mt][2 * g],     ah[mt], &bl[g][0]);
                    mma16816(acc[mt][2 * g],     al[mt], &bh[g][0]);
                    mma16816(acc[mt][2 * g + 1], ah[mt], &bh[g][2]);
                    mma16816(acc[mt][2 * g + 1], ah[mt], &bl[g][2]);
                    mma16816(acc[mt][2 * g + 1], al[mt], &bh[g][2]);
                }
        }
    }

    // ---- epilogue: LN correction + store ----
    float* outB = (N0 < DH) ? d_kf : d_vf;
    int cbase = (N0 < DH) ? N0 : N0 - DH;
#pragma unroll
    for (int mt = 0; mt < 2; mt++) {
        long gr0 = row0 + m0 + mt * 16 + (l >> 2);
        long gr1 = gr0 + 8;
        float mean0 = d_stats[2 * gr0], rst0 = d_stats[2 * gr0 + 1];
        float mean1 = d_stats[2 * gr1], rst1 = d_stats[2 * gr1 + 1];
#pragma unroll
        for (int j = 0; j < 4; j++) {
            int nrel = n0w + (j >> 1) * 16 + (j & 1) * 8 + 2 * (l & 3);
            int jg = N0 + nrel;
            float wg0 = d_wgsum[jg], wg1 = d_wgsum[jg + 1];
            float wb0 = d_wb[jg],    wb1 = d_wb[jg + 1];
            int col = cbase + nrel;
            float2 o0, o1;
            o0.x = rst0 * (acc[mt][j][0] - mean0 * wg0) + wb0;
            o0.y = rst0 * (acc[mt][j][1] - mean0 * wg1) + wb1;
            o1.x = rst1 * (acc[mt][j][2] - mean1 * wg0) + wb0;
            o1.y = rst1 * (acc[mt][j][3] - mean1 * wg1) + wb1;
            *(float2*)(outB + gr0 * 256 + col) = o0;
            *(float2*)(outB + gr1 * 256 + col) = o1;
        }
    }
}

// ---------------- kernel 4: copy prev_slots into working slots -------------
__global__ void copy_slots(const float* __restrict__ prev) {
    int i = blockIdx.x * 256 + threadIdx.x;
    d_slots[i] = prev[i];
}

// ---------------- kernel 5: per-batch q projection (+ acc zeroing) ---------
__global__ __launch_bounds__(256) void slot_q_all(const float* __restrict__ g_s,
                                                  const float* __restrict__ b_s,
                                                  const float* __restrict__ Wq) {
    int b = blockIdx.x;
    int t = threadIdx.x, w = t >> 5, l = t & 31;
    __shared__ float sn[KS][DS];
    __shared__ float mrs[KS][2];

    // zero this batch's accumulators (consumed by attn kernels after this)
#pragma unroll
    for (int j = 0; j < 8; j++) d_U[b * (KS * DS) + j * 256 + t] = 0.f;
    if (t < KS) { d_S[b * KS + t] = 0.f; d_msum[b * KS + t] = 0.f; }

    // LN stats: warp w owns slot-row w
    {
        const float* sr = d_slots + (b * KS + w) * DS;
        float s = 0.f, s2 = 0.f;
#pragma unroll
        for (int j = 0; j < 8; j++) {
            float v = sr[l + 32 * j];
            s += v; s2 += v * v;
        }
#pragma unroll
        for (int o = 16; o; o >>= 1) {
            s  += __shfl_xor_sync(~0u, s, o);
            s2 += __shfl_xor_sync(~0u, s2, o);
        }
        if (l == 0) {
            float m = s * (1.f / DS);
            float var = s2 * (1.f / DS) - m * m;
            mrs[w][0] = m;
            mrs[w][1] = rsqrtf(var + LNEPS);
        }
    }
    __syncthreads();
    float gt = g_s[t], bt = b_s[t];
#pragma unroll
    for (int k = 0; k < KS; k++)
        sn[k][t] = (d_slots[(b * KS + k) * DS + t] - mrs[k][0]) * mrs[k][1] * gt + bt;
    __syncthreads();

    float acc[KS];
#pragma unroll
    for (int k = 0; k < KS; k++) acc[k] = 0.f;
    const float4* wq4 = (const float4*)(Wq + (long)t * DS);
#pragma unroll 4
    for (int d4 = 0; d4 < 64; d4++) {
        float4 wv = wq4[d4];
#pragma unroll
        for (int k = 0; k < KS; k++) {
            float4 sv = *(const float4*)&sn[k][d4 * 4];
            acc[k] += wv.x * sv.x + wv.y * sv.y + wv.z * sv.z + wv.w * sv.w;
        }
    }
#pragma unroll
    for (int k = 0; k < KS; k++) d_q[(b * KS + k) * DH + t] = acc[k];
}

// ---------------- kernel 6: attention + unnormalized update accumulation ---
__global__ __launch_bounds__(256) void attn_iter() {
    int b = blockIdx.y;
    int n0 = blockIdx.x * 256;
    int t = threadIdx.x, w = t >> 5, l = t & 31;
    __shared__ float qs[KS][DS];
#pragma unroll
    for (int k = 0; k < KS; k++) qs[k][t] = d_q[(b * KS + k) * DH + t];
    __syncthreads();

    float accU[KS][8];
    float sacc[KS];
#pragma unroll
    for (int k = 0; k < KS; k++) {
        sacc[k] = 0.f;
#pragma unroll
        for (int i = 0; i < 8; i++) accU[k][i] = 0.f;
    }

    for (int ni = 0; ni < 32; ni++) {
        int n = n0 + w * 32 + ni;
        long base = ((long)b * NTOK + n) * DH;
        float kf[8];
#pragma unroll
        for (int i = 0; i < 8; i++) kf[i] = d_kf[base + i * 32 + l];
        float lg[KS];
#pragma unroll
        for (int k = 0; k < KS; k++) lg[k] = 0.f;
#pragma unroll
        for (int i = 0; i < 8; i++) {
            float kv = kf[i];
            int d = i * 32 + l;
#pragma unroll
            for (int k = 0; k < KS; k++) lg[k] = fmaf(qs[k][d], kv, lg[k]);
        }
#pragma unroll
        for (int o = 16; o; o >>= 1)
#pragma unroll
            for (int k = 0; k < KS; k++) lg[k] += __shfl_xor_sync(~0u, lg[k], o);
#pragma unroll
        for (int k = 0; k < KS; k++) lg[k] *= ATT_SCALE;
        float mx = lg[0];
#pragma unroll
        for (int k = 1; k < KS; k++) mx = fmaxf(mx, lg[k]);
        float e[KS], se = 0.f;
#pragma unroll
        for (int k = 0; k < KS; k++) { e[k] = __expf(lg[k] - mx); se += e[k]; }
        float inv = 1.f / se;
        float vf[8];
#pragma unroll
        for (int i = 0; i < 8; i++) vf[i] = d_vf[base + i * 32 + l];
#pragma unroll
        for (int k = 0; k < KS; k++) {
            float a = e[k] * inv;
            sacc[k] += a;
#pragma unroll
            for (int i = 0; i < 8; i++) accU[k][i] = fmaf(a, vf[i], accU[k][i]);
        }
    }
#pragma unroll
    for (int k = 0; k < KS; k++) {
#pragma unroll
        for (int i = 0; i < 8; i++)
            atomicAdd(&d_U[(b * KS + k) * DS + i * 32 + l], accU[k][i]);
        if (l == 0) atomicAdd(&d_S[b * KS + k], sacc[k]);
    }
}

// ---------------- kernel 7: final attention (writes attn + mask sums) ------
__global__ __launch_bounds__(256) void attn_final(float* __restrict__ attn_out) {
    int b = blockIdx.y;
    int n0 = blockIdx.x * 256;
    int t = threadIdx.x, w = t >> 5, l = t & 31;
    __shared__ float qs[KS][DS];
    __shared__ float as_[KS][256];
#pragma unroll
    for (int k = 0; k < KS; k++) qs[k][t] = d_q[(b * KS + k) * DH + t];
    __syncthreads();

    float sacc[KS];
#pragma unroll
    for (int k = 0; k < KS; k++) sacc[k] = 0.f;

    for (int ni = 0; ni < 32; ni++) {
        int nl = w * 32 + ni;
        int n = n0 + nl;
        long base = ((long)b * NTOK + n) * DH;
        float kf[8];
#pragma unroll
        for (int i = 0; i < 8; i++) kf[i] = d_kf[base + i * 32 + l];
        float lg[KS];
#pragma unroll
        for (int k = 0; k < KS; k++) lg[k] = 0.f;
#pragma unroll
        for (int i = 0; i < 8; i++) {
            float kv = kf[i];
            int d = i * 32 + l;
#pragma unroll
            for (int k = 0; k < KS; k++) lg[k] = fmaf(qs[k][d], kv, lg[k]);
        }
#pragma unroll
        for (int o = 16; o; o >>= 1)
#pragma unroll
            for (int k = 0; k < KS; k++) lg[k] += __shfl_xor_sync(~0u, lg[k], o);
#pragma unroll
        for (int k = 0; k < KS; k++) lg[k] *= ATT_SCALE;
        float mx = lg[0];
#pragma unroll
        for (int k = 1; k < KS; k++) mx = fmaxf(mx, lg[k]);
        float e[KS], se = 0.f;
#pragma unroll
        for (int k = 0; k < KS; k++) { e[k] = __expf(lg[k] - mx); se += e[k]; }
        float inv = 1.f / se;
#pragma unroll
        for (int k = 0; k < KS; k++) {
            float a = e[k] * inv;
            sacc[k] += a;
            if (l == (unsigned)k) as_[k][nl] = a;
        }
    }
    __syncthreads();
#pragma unroll
    for (int k = 0; k < KS; k++)
        attn_out[((long)(b * KS + k)) * NTOK + n0 + t] = as_[k][t];
    if (l == 0)
#pragma unroll
        for (int k = 0; k < KS; k++) atomicAdd(&d_msum[b * KS + k], sacc[k]);
}

// ---------------- kernel 8: per-batch GRU + LN + MLP slot update -----------
__global__ __launch_bounds__(256) void slot_upd_all(
    const float* __restrict__ W_ih, const float* __restrict__ W_hh,
    const float* __restrict__ b_ih, const float* __restrict__ b_hh,
    const float* __restrict__ g_m, const float* __restrict__ b_m,
    const float* __restrict__ W1, const float* __restrict__ b1,
    const float* __restrict__ W2, const float* __restrict__ b2) {
    int b = blockIdx.x;
    int t = threadIdx.x, w = t >> 5, l = t & 31;
    __shared__ float u[KS][DS];    // updates, then reused as h
    __shared__ float so[KS][DS];
    __shared__ float hn[KS][DS];
    __shared__ float m1[KS][DS];
    __shared__ float mrs[KS][2];

#pragma unroll
    for (int k = 0; k < KS; k++) {
        float Sv = d_S[b * KS + k] + EPSV;
        u[k][t]  = d_U[(b * KS + k) * DS + t] / Sv;
        so[k][t] = d_slots[(b * KS + k) * DS + t];
    }
    __syncthreads();

    // gates: thread t owns gate rows t, t+256, t+512
    float gi[3][KS], gh[3][KS];
#pragma unroll
    for (int g = 0; g < 3; g++)
#pragma unroll
        for (int k = 0; k < KS; k++) { gi[g][k] = 0.f; gh[g][k] = 0.f; }

    const float4* wi0 = (const float4*)(W_ih + (long)t * DS);
    const float4* wi1 = (const float4*)(W_ih + (long)(DS + t) * DS);
    const float4* wi2 = (const float4*)(W_ih + (long)(2 * DS + t) * DS);
    const float4* wh0 = (const float4*)(W_hh + (long)t * DS);
    const float4* wh1 = (const float4*)(W_hh + (long)(DS + t) * DS);
    const float4* wh2 = (const float4*)(W_hh + (long)(2 * DS + t) * DS);
    for (int d4 = 0; d4 < 64; d4++) {
        float4 a0 = wi0[d4], a1 = wi1[d4], a2 = wi2[d4];
        float4 c0 = wh0[d4], c1 = wh1[d4], c2 = wh2[d4];
#pragma unroll
        for (int k = 0; k < KS; k++) {
            float4 uv = *(const float4*)&u[k][d4 * 4];
            float4 sv = *(const float4*)&so[k][d4 * 4];
            gi[0][k] += a0.x * uv.x + a0.y * uv.y + a0.z * uv.z + a0.w * uv.w;
            gi[1][k] += a1.x * uv.x + a1.y * uv.y + a1.z * uv.z + a1.w * uv.w;
            gi[2][k] += a2.x * uv.x + a2.y * uv.y + a2.z * uv.z + a2.w * uv.w;
            gh[0][k] += c0.x * sv.x + c0.y * sv.y + c0.z * sv.z + c0.w * sv.w;
            gh[1][k] += c1.x * sv.x + c1.y * sv.y + c1.z * sv.z + c1.w * sv.w;
            gh[2][k] += c2.x * sv.x + c2.y * sv.y + c2.z * sv.z + c2.w * sv.w;
        }
    }
    float bi0 = b_ih[t], bi1 = b_ih[DS + t], bi2 = b_ih[2 * DS + t];
    float bh0 = b_hh[t], bh1 = b_hh[DS + t], bh2 = b_hh[2 * DS + t];
    __syncthreads();   // all reads of u done before overwrite with h
#pragma unroll
    for (int k = 0; k < KS; k++) {
        float r  = 1.f / (1.f + __expf(-(gi[0][k] + bi0 + gh[0][k] + bh0)));
        float z  = 1.f / (1.f + __expf(-(gi[1][k] + bi1 + gh[1][k] + bh1)));
        float nn = tanhf(gi[2][k] + bi2 + r * (gh[2][k] + bh2));
        u[k][t] = (1.f - z) * nn + z * so[k][t];   // h
    }
    __syncthreads();

    // LN(h): warp w owns row w
    {
        float s = 0.f, s2 = 0.f;
#pragma unroll
        for (int j = 0; j < 8; j++) {
            float v = u[w][l + 32 * j];
            s += v; s2 += v * v;
        }
#pragma unroll
        for (int o = 16; o; o >>= 1) {
            s  += __shfl_xor_sync(~0u, s, o);
            s2 += __shfl_xor_sync(~0u, s2, o);
        }
        if (l == 0) {
            float m = s * (1.f / DS);
            float var = s2 * (1.f / DS) - m * m;
            mrs[w][0] = m;
            mrs[w][1] = rsqrtf(var + LNEPS);
        }
    }
    __syncthreads();
    float gmt = g_m[t], bmt = b_m[t];
#pragma unroll
    for (int k = 0; k < KS; k++)
        hn[k][t] = (u[k][t] - mrs[k][0]) * mrs[k][1] * gmt + bmt;
    __syncthreads();

    // MLP layer 1
    {
        float a1[KS];
#pragma unroll
        for (int k = 0; k < KS; k++) a1[k] = 0.f;
        const float4* w14 = (const float4*)(W1 + (long)t * DS);
        for (int d4 = 0; d4 < 64; d4++) {
            float4 wv = w14[d4];
#pragma unroll
            for (int k = 0; k < KS; k++) {
                float4 hv = *(const float4*)&hn[k][d4 * 4];
                a1[k] += wv.x * hv.x + wv.y * hv.y + wv.z * hv.z + wv.w * hv.w;
            }
        }
        float b1t = b1[t];
#pragma unroll
        for (int k = 0; k < KS; k++) m1[k][t] = fmaxf(a1[k] + b1t, 0.f);
    }
    __syncthreads();
    // MLP layer 2 + residual
    {
        float a2[KS];
#pragma unroll
        for (int k = 0; k < KS; k++) a2[k] = 0.f;
        const float4* w24 = (const float4*)(W2 + (long)t * DS);
        for (int d4 = 0; d4 < 64; d4++) {
            float4 wv = w24[d4];
#pragma unroll
            for (int k = 0; k < KS; k++) {
                float4 mv = *(const float4*)&m1[k][d4 * 4];
                a2[k] += wv.x * mv.x + wv.y * mv.y + wv.z * mv.z + wv.w * mv.w;
            }
        }
        float b2t = b2[t];
#pragma unroll
        for (int k = 0; k < KS; k++)
            d_slots[(b * KS + k) * DS + t] = u[k][t] + a2[k] + b2t;
    }
}

// ---------------- kernel 9: confidence blend -------------------------------
__global__ void blend(const float* __restrict__ prev, float* __restrict__ out) {
    int i = blockIdx.x * 256 + threadIdx.x;
    int bk = i >> 8;
    float mask = 1.f / (1.f + __expf(-d_msum[bk] * (1.f / NTOK)));
    out[i] = d_slots[i] * mask + prev[i] * (1.f - mask);
}

// ---------------- launch ---------------------------------------------------
extern "C" void kernel_launch(void* const* d_in, const int* in_sizes, int n_in,
                              void* d_out, int out_size) {
    const float* features  = (const float*)d_in[0];
    const float* prev      = (const float*)d_in[1];
    const float* g_in      = (const float*)d_in[2];
    const float* b_in      = (const float*)d_in[3];
    const float* g_s       = (const float*)d_in[4];
    const float* b_s       = (const float*)d_in[5];
    const float* g_m       = (const float*)d_in[6];
    const float* b_m       = (const float*)d_in[7];
    const float* Wq        = (const float*)d_in[8];
    const float* Wk        = (const float*)d_in[9];
    const float* Wv        = (const float*)d_in[10];
    const float* W_ih      = (const float*)d_in[11];
    const float* W_hh      = (const float*)d_in[12];
    const float* b_ih      = (const float*)d_in[13];
    const float* b_hh      = (const float*)d_in[14];
    const float* W1        = (const float*)d_in[15];
    const float* b1        = (const float*)d_in[16];
    const float* W2        = (const float*)d_in[17];
    const float* b2        = (const float*)d_in[18];

    float* out      = (float*)d_out;
    float* attn_out = out + B * KS * DS;

    cudaFuncSetAttribute(kv_gemm_mma, cudaFuncAttributeMaxDynamicSharedMemorySize, SMEM_GEMM);

    prep_weights<<<DH + DS, 256>>>(Wk, Wv, g_in, b_in);
    row_stats_cvt<<<B * NTOK / 8, 256>>>(features);
    kv_gemm_mma<<<dim3(4, B * NTOK / 64), 256, SMEM_GEMM>>>();
    copy_slots<<<B * KS * DS / 256, 256>>>(prev);

    for (int it = 0; it < NITER; it++) {
        slot_q_all<<<B, 256>>>(g_s, b_s, Wq);
        attn_iter<<<dim3(NTOK / 256, B), 256>>>();
        slot_upd_all<<<B, 256>>>(W_ih, W_hh, b_ih, b_hh, g_m, b_m, W1, b1, W2, b2);
    }
    slot_q_all<<<B, 256>>>(g_s, b_s, Wq);
    attn_final<<<dim3(NTOK / 256, B), 256>>>(attn_out);
    blend<<<B * KS * DS / 256, 256>>>(prev, out);
}

// round 8
// speedup vs baseline: 1.5346x; 1.5346x over previous
#include <cuda_runtime.h>
#include <cuda_bf16.h>
#include <math.h>
#include <stdint.h>

#define B 32
#define NTOK 4096
#define DF 768
#define KS 8
#define DS 256
#define DH 256
#define NITER 3
#define EPSV 1e-8f
#define LNEPS 1e-5f
#define ATT_SCALE 0.0625f   // 256^-0.5

// ---------------- scratch (device globals; no allocation allowed) ----------
__device__ __align__(16) float d_stats[B * NTOK * 2];
__device__ __align__(16) float d_kf[(long)B * NTOK * DH];     // 134 MB
__device__ __align__(16) float d_vf[(long)B * NTOK * DS];     // 134 MB
__device__ __align__(16) __nv_bfloat16 d_Wh[(DH + DS) * DF];
__device__ __align__(16) __nv_bfloat16 d_Wl[(DH + DS) * DF];
__device__ __align__(16) float d_wgsum[DH + DS];
__device__ __align__(16) float d_wb[DH + DS];
__device__ __align__(16) float d_slots[B * KS * DS];
__device__ __align__(16) float d_q[B * KS * DH];
__device__ __align__(16) float d_U[B * KS * DS];
__device__ __align__(16) float d_S[B * KS];
__device__ __align__(16) float d_msum[B * KS];

// ================= mma.sync helpers (sm_80 baseline) ========================
__device__ __forceinline__ void ldsm4(uint32_t* r, uint32_t addr) {
    asm volatile("ldmatrix.sync.aligned.m8n8.x4.shared.b16 {%0,%1,%2,%3}, [%4];"
        : "=r"(r[0]), "=r"(r[1]), "=r"(r[2]), "=r"(r[3]) : "r"(addr));
}
__device__ __forceinline__ void mma16816(float* c, const uint32_t* a, const uint32_t* b) {
    asm volatile("mma.sync.aligned.m16n8k16.row.col.f32.bf16.bf16.f32 "
        "{%0,%1,%2,%3}, {%4,%5,%6,%7}, {%8,%9}, {%0,%1,%2,%3};"
        : "+f"(c[0]), "+f"(c[1]), "+f"(c[2]), "+f"(c[3])
        : "r"(a[0]), "r"(a[1]), "r"(a[2]), "r"(a[3]), "r"(b[0]), "r"(b[1]));
}
#define CPA(dst, src) asm volatile("cp.async.cg.shared.global [%0], [%1], 16;" :: "r"(dst), "l"(src))
#define CPC() asm volatile("cp.async.commit_group;" ::: "memory")
#define CPW2() asm volatile("cp.async.wait_group 2;" ::: "memory")
__device__ __forceinline__ uint32_t smem_u32(const void* p) {
    uint32_t a;
    asm("{ .reg .u64 t; cvta.to.shared.u64 t, %1; cvt.u32.u64 %0, t; }" : "=r"(a) : "l"(p));
    return a;
}

// ---------------- kernel 1: fold LN gain, build bf16 hi/lo weights ---------
__global__ void prep_weights(const float* __restrict__ Wk, const float* __restrict__ Wv,
                             const float* __restrict__ g_in, const float* __restrict__ b_in) {
    int j = blockIdx.x;            // 0..511
    int t = threadIdx.x;           // 256 threads
    const float* wrow = (j < DH) ? (Wk + (long)j * DF) : (Wv + (long)(j - DH) * DF);
    float sg = 0.f, sb = 0.f;
    for (int d = t; d < DF; d += 256) {
        float w = wrow[d];
        float g = g_in[d];
        float wg = w * g;
        __nv_bfloat16 hi = __float2bfloat16_rn(wg);
        d_Wh[(long)j * DF + d] = hi;
        d_Wl[(long)j * DF + d] = __float2bfloat16_rn(wg - __bfloat162float(hi));
        sg += wg;
        sb += w * b_in[d];
    }
    __shared__ float red[64];
#pragma unroll
    for (int o = 16; o; o >>= 1) {
        sg += __shfl_xor_sync(~0u, sg, o);
        sb += __shfl_xor_sync(~0u, sb, o);
    }
    int w = t >> 5, l = t & 31;
    if (l == 0) { red[w] = sg; red[32 + w] = sb; }
    __syncthreads();
    if (t == 0) {
        float a = 0.f, c = 0.f;
        for (int i = 0; i < 8; i++) { a += red[i]; c += red[32 + i]; }
        d_wgsum[j] = a;
        d_wb[j] = c;
    }
}

// ---------------- kernel 2: per-row mean / rstd of features ----------------
__global__ void row_stats(const float* __restrict__ feat) {
    int w = threadIdx.x >> 5, l = threadIdx.x & 31;
    long row = (long)blockIdx.x * 8 + w;
    const float4* x = (const float4*)(feat + row * DF);
    float s = 0.f, s2 = 0.f;
#pragma unroll
    for (int i = 0; i < 6; i++) {
        float4 v = x[l + 32 * i];
        s  += v.x + v.y + v.z + v.w;
        s2 += v.x * v.x + v.y * v.y + v.z * v.z + v.w * v.w;
    }
#pragma unroll
    for (int o = 16; o; o >>= 1) {
        s  += __shfl_xor_sync(~0u, s, o);
        s2 += __shfl_xor_sync(~0u, s2, o);
    }
    if (l == 0) {
        float m = s * (1.f / DF);
        float var = s2 * (1.f / DF) - m * m;
        d_stats[2 * row]     = m;
        d_stats[2 * row + 1] = rsqrtf(var + LNEPS);
    }
}

// ---------------- kernel 3: mma.sync bf16x3 fused LN + K/V GEMM ------------
// C(131072 x 512) = X @ Wg^T. CTA 128M x 128N, K-chunk 32, 4-stage pipeline.
// Stage: Ah | Al | Bh | Bl, each 128 rows x 80B (32 bf16 + 16B pad) = 10240B.
#define KCH 32
#define NCHUNKS 24
#define A_HI 0
#define A_LO 10240
#define B_HI 20480
#define B_LO 30720
#define STG  40960
#define NSTAGE 4
#define SMEM_GEMM (NSTAGE * STG)

__global__ void __launch_bounds__(256, 1) kv_gemm_mma(const float* __restrict__ X) {
    extern __shared__ char sm[];
    uint32_t sb = smem_u32(sm);
    int t = threadIdx.x;
    int w = t >> 5, l = t & 31;
    int wm = w & 3, wn = w >> 2;           // 4 m-warps x 2 n-warps
    int m0 = wm * 32, n0w = wn * 64;
    int N0 = blockIdx.x * 128;             // N fastest -> co-resident CTAs share X in L2
    long row0 = (long)blockIdx.y * 128;

    // producer indexing
    int arow = t >> 1, ahalf = t & 1;
    const float* aptr = X + (row0 + arow) * (long)DF + ahalf * 16;
    char* a_st = sm + arow * 80 + ahalf * 32;
    int bn = t >> 2, bc = t & 3;
    const __nv_bfloat16* bhs0 = d_Wh + (size_t)(N0 + bn) * DF + bc * 8;
    const __nv_bfloat16* bhs1 = d_Wh + (size_t)(N0 + 64 + bn) * DF + bc * 8;
    const __nv_bfloat16* bls0 = d_Wl + (size_t)(N0 + bn) * DF + bc * 8;
    const __nv_bfloat16* bls1 = d_Wl + (size_t)(N0 + 64 + bn) * DF + bc * 8;
    uint32_t b_st0 = sb + bn * 80 + bc * 16;
    uint32_t b_st1 = sb + (64 + bn) * 80 + bc * 16;

    // consumer ldmatrix bases
    uint32_t aA = sb + (uint32_t)((m0 + (l & 15)) * 80 + (l >> 4) * 16);
    uint32_t aB = sb + (uint32_t)(B_HI + (n0w + (l & 7) + ((l >> 4) & 1) * 8) * 80 + ((l >> 3) & 1) * 16);

    float acc[2][8][4];
#pragma unroll
    for (int i = 0; i < 2; i++)
#pragma unroll
        for (int j = 0; j < 8; j++)
#pragma unroll
            for (int q = 0; q < 4; q++) acc[i][j][q] = 0.f;

    float4 af[4];

#define LOAD_A(c) { const float4* s4_ = (const float4*)(aptr + (c) * KCH); \
    af[0] = s4_[0]; af[1] = s4_[1]; af[2] = s4_[2]; af[3] = s4_[3]; }

#define STORE_A(soff) { \
    const float* f_ = (const float*)af; \
    uint32_t H_[8], L_[8]; \
    _Pragma("unroll") for (int i_ = 0; i_ < 8; i_++) { \
        float a_ = f_[2*i_], b_ = f_[2*i_+1]; \
        __nv_bfloat162 hp_, lp_; \
        hp_.x = __float2bfloat16_rn(a_); hp_.y = __float2bfloat16_rn(b_); \
        lp_.x = __float2bfloat16_rn(a_ - __bfloat162float(hp_.x)); \
        lp_.y = __float2bfloat16_rn(b_ - __bfloat162float(hp_.y)); \
        H_[i_] = *(uint32_t*)&hp_; L_[i_] = *(uint32_t*)&lp_; \
    } \
    *(uint4*)(a_st + (soff) + A_HI)      = make_uint4(H_[0], H_[1], H_[2], H_[3]); \
    *(uint4*)(a_st + (soff) + A_HI + 16) = make_uint4(H_[4], H_[5], H_[6], H_[7]); \
    *(uint4*)(a_st + (soff) + A_LO)      = make_uint4(L_[0], L_[1], L_[2], L_[3]); \
    *(uint4*)(a_st + (soff) + A_LO + 16) = make_uint4(L_[4], L_[5], L_[6], L_[7]); }

#define ISSUE_B(soff, c) { \
    CPA(b_st0 + (soff) + B_HI, bhs0 + (c) * KCH); \
    CPA(b_st1 + (soff) + B_HI, bhs1 + (c) * KCH); \
    CPA(b_st0 + (soff) + B_LO, bls0 + (c) * KCH); \
    CPA(b_st1 + (soff) + B_LO, bls1 + (c) * KCH); }

    // prologue: chunks 0..2 into stages 0..2
    ISSUE_B(0, 0); CPC();
    ISSUE_B(STG, 1); CPC();
    ISSUE_B(2 * STG, 2); CPC();
    LOAD_A(0); STORE_A(0);
    LOAD_A(1); STORE_A(STG);
    LOAD_A(2); STORE_A(2 * STG);

    for (int c = 0; c < NCHUNKS; c++) {
        uint32_t soff = (uint32_t)(c % NSTAGE) * STG;
        CPW2();
        __syncthreads();
        int cn = c + 3;
        uint32_t snoff = (uint32_t)(cn % NSTAGE) * STG;
        if (cn < NCHUNKS) {
            LOAD_A(cn);
            ISSUE_B(snoff, cn);
        }
        CPC();
        // ---- mma on stage c%NSTAGE ----
#pragma unroll
        for (int k16 = 0; k16 < 2; k16++) {
            uint32_t ah[2][4], al[2][4];
            ldsm4(ah[0], aA + soff + A_HI + k16 * 32);
            ldsm4(ah[1], aA + soff + A_HI + 16 * 80 + k16 * 32);
            ldsm4(al[0], aA + soff + A_LO + k16 * 32);
            ldsm4(al[1], aA + soff + A_LO + 16 * 80 + k16 * 32);
            uint32_t bh[4][4], bl[4][4];
#pragma unroll
            for (int g = 0; g < 4; g++) {
                ldsm4(bh[g], aB + soff + g * (16 * 80) + k16 * 32);
                ldsm4(bl[g], aB + soff + (B_LO - B_HI) + g * (16 * 80) + k16 * 32);
            }
#pragma unroll
            for (int mt = 0; mt < 2; mt++)
#pragma unroll
                for (int g = 0; g < 4; g++) {
                    mma16816(acc[mt][2 * g],     ah[mt], &bh[g][0]);
                    mma16816(acc[mt][2 * g],     ah[mt], &bl[g][0]);
                    mma16816(acc[mt][2 * g],     al[mt], &bh[g][0]);
                    mma16816(acc[mt][2 * g + 1], ah[mt], &bh[g][2]);
                    mma16816(acc[mt][2 * g + 1], ah[mt], &bl[g][2]);
                    mma16816(acc[mt][2 * g + 1], al[mt], &bh[g][2]);
                }
        }
        if (cn < NCHUNKS) STORE_A(snoff);
    }

    // ---- epilogue: LN correction + store to d_kf / d_vf ----
#pragma unroll
    for (int mt = 0; mt < 2; mt++) {
        long gr0 = row0 + m0 + mt * 16 + (l >> 2);
        long gr1 = gr0 + 8;
        float mean0 = d_stats[2 * gr0], rst0 = d_stats[2 * gr0 + 1];
        float mean1 = d_stats[2 * gr1], rst1 = d_stats[2 * gr1 + 1];
#pragma unroll
        for (int nt = 0; nt < 8; nt++) {
            int jl = N0 + n0w + nt * 8 + 2 * (l & 3);
            float wg0 = d_wgsum[jl], wg1 = d_wgsum[jl + 1];
            float wb0 = d_wb[jl],    wb1 = d_wb[jl + 1];
            float* outp; int col;
            if (jl < DH) { outp = d_kf; col = jl; } else { outp = d_vf; col = jl - DH; }
            float2 o0, o1;
            o0.x = rst0 * (acc[mt][nt][0] - mean0 * wg0) + wb0;
            o0.y = rst0 * (acc[mt][nt][1] - mean0 * wg1) + wb1;
            o1.x = rst1 * (acc[mt][nt][2] - mean1 * wg0) + wb0;
            o1.y = rst1 * (acc[mt][nt][3] - mean1 * wg1) + wb1;
            *(float2*)(outp + gr0 * 256 + col) = o0;
            *(float2*)(outp + gr1 * 256 + col) = o1;
        }
    }
}

// ---------------- kernel 4: copy prev_slots into working slots -------------
__global__ void copy_slots(const float* __restrict__ prev) {
    int i = blockIdx.x * 256 + threadIdx.x;
    d_slots[i] = prev[i];
}

// ---------------- kernel 5: per-batch q projection (+ acc zeroing) ---------
__global__ __launch_bounds__(256) void slot_q_all(const float* __restrict__ g_s,
                                                  const float* __restrict__ b_s,
                                                  const float* __restrict__ Wq) {
    int b = blockIdx.x;
    int t = threadIdx.x, w = t >> 5, l = t & 31;
    __shared__ float sn[KS][DS];
    __shared__ float mrs[KS][2];

#pragma unroll
    for (int j = 0; j < 8; j++) d_U[b * (KS * DS) + j * 256 + t] = 0.f;
    if (t < KS) { d_S[b * KS + t] = 0.f; d_msum[b * KS + t] = 0.f; }

    {
        const float* sr = d_slots + (b * KS + w) * DS;
        float s = 0.f, s2 = 0.f;
#pragma unroll
        for (int j = 0; j < 8; j++) {
            float v = sr[l + 32 * j];
            s += v; s2 += v * v;
        }
#pragma unroll
        for (int o = 16; o; o >>= 1) {
            s  += __shfl_xor_sync(~0u, s, o);
            s2 += __shfl_xor_sync(~0u, s2, o);
        }
        if (l == 0) {
            float m = s * (1.f / DS);
            float var = s2 * (1.f / DS) - m * m;
            mrs[w][0] = m;
            mrs[w][1] = rsqrtf(var + LNEPS);
        }
    }
    __syncthreads();
    float gt = g_s[t], bt = b_s[t];
#pragma unroll
    for (int k = 0; k < KS; k++)
        sn[k][t] = (d_slots[(b * KS + k) * DS + t] - mrs[k][0]) * mrs[k][1] * gt + bt;
    __syncthreads();

    float acc[KS];
#pragma unroll
    for (int k = 0; k < KS; k++) acc[k] = 0.f;
    const float4* wq4 = (const float4*)(Wq + (long)t * DS);
#pragma unroll 4
    for (int d4 = 0; d4 < 64; d4++) {
        float4 wv = wq4[d4];
#pragma unroll
        for (int k = 0; k < KS; k++) {
            float4 sv = *(const float4*)&sn[k][d4 * 4];
            acc[k] += wv.x * sv.x + wv.y * sv.y + wv.z * sv.z + wv.w * sv.w;
        }
    }
#pragma unroll
    for (int k = 0; k < KS; k++) d_q[(b * KS + k) * DH + t] = acc[k];
}

// ---------------- kernel 6: attention + unnormalized update accumulation ---
__global__ __launch_bounds__(256) void attn_iter() {
    int b = blockIdx.y;
    int n0 = blockIdx.x * 256;
    int t = threadIdx.x, w = t >> 5, l = t & 31;
    __shared__ float qs[KS][DS];
#pragma unroll
    for (int k = 0; k < KS; k++) qs[k][t] = d_q[(b * KS + k) * DH + t];
    __syncthreads();

    float accU[KS][8];
    float sacc[KS];
#pragma unroll
    for (int k = 0; k < KS; k++) {
        sacc[k] = 0.f;
#pragma unroll
        for (int i = 0; i < 8; i++) accU[k][i] = 0.f;
    }

    for (int ni = 0; ni < 32; ni++) {
        int n = n0 + w * 32 + ni;
        long base = ((long)b * NTOK + n) * DH;
        float kf[8];
#pragma unroll
        for (int i = 0; i < 8; i++) kf[i] = d_kf[base + i * 32 + l];
        float lg[KS];
#pragma unroll
        for (int k = 0; k < KS; k++) lg[k] = 0.f;
#pragma unroll
        for (int i = 0; i < 8; i++) {
            float kv = kf[i];
            int d = i * 32 + l;
#pragma unroll
            for (int k = 0; k < KS; k++) lg[k] = fmaf(qs[k][d], kv, lg[k]);
        }
#pragma unroll
        for (int o = 16; o; o >>= 1)
#pragma unroll
            for (int k = 0; k < KS; k++) lg[k] += __shfl_xor_sync(~0u, lg[k], o);
#pragma unroll
        for (int k = 0; k < KS; k++) lg[k] *= ATT_SCALE;
        float mx = lg[0];
#pragma unroll
        for (int k = 1; k < KS; k++) mx = fmaxf(mx, lg[k]);
        float e[KS], se = 0.f;
#pragma unroll
        for (int k = 0; k < KS; k++) { e[k] = __expf(lg[k] - mx); se += e[k]; }
        float inv = 1.f / se;
        float vf[8];
#pragma unroll
        for (int i = 0; i < 8; i++) vf[i] = d_vf[base + i * 32 + l];
#pragma unroll
        for (int k = 0; k < KS; k++) {
            float a = e[k] * inv;
            sacc[k] += a;
#pragma unroll
            for (int i = 0; i < 8; i++) accU[k][i] = fmaf(a, vf[i], accU[k][i]);
        }
    }
#pragma unroll
    for (int k = 0; k < KS; k++) {
#pragma unroll
        for (int i = 0; i < 8; i++)
            atomicAdd(&d_U[(b * KS + k) * DS + i * 32 + l], accU[k][i]);
        if (l == 0) atomicAdd(&d_S[b * KS + k], sacc[k]);
    }
}

// ---------------- kernel 7: final attention (writes attn + mask sums) ------
__global__ __launch_bounds__(256) void attn_final(float* __restrict__ attn_out) {
    int b = blockIdx.y;
    int n0 = blockIdx.x * 256;
    int t = threadIdx.x, w = t >> 5, l = t & 31;
    __shared__ float qs[KS][DS];
    __shared__ float as_[KS][256];
#pragma unroll
    for (int k = 0; k < KS; k++) qs[k][t] = d_q[(b * KS + k) * DH + t];
    __syncthreads();

    float sacc[KS];
#pragma unroll
    for (int k = 0; k < KS; k++) sacc[k] = 0.f;

    for (int ni = 0; ni < 32; ni++) {
        int nl = w * 32 + ni;
        int n = n0 + nl;
        long base = ((long)b * NTOK + n) * DH;
        float kf[8];
#pragma unroll
        for (int i = 0; i < 8; i++) kf[i] = d_kf[base + i * 32 + l];
        float lg[KS];
#pragma unroll
        for (int k = 0; k < KS; k++) lg[k] = 0.f;
#pragma unroll
        for (int i = 0; i < 8; i++) {
            float kv = kf[i];
            int d = i * 32 + l;
#pragma unroll
            for (int k = 0; k < KS; k++) lg[k] = fmaf(qs[k][d], kv, lg[k]);
        }
#pragma unroll
        for (int o = 16; o; o >>= 1)
#pragma unroll
            for (int k = 0; k < KS; k++) lg[k] += __shfl_xor_sync(~0u, lg[k], o);
#pragma unroll
        for (int k = 0; k < KS; k++) lg[k] *= ATT_SCALE;
        float mx = lg[0];
#pragma unroll
        for (int k = 1; k < KS; k++) mx = fmaxf(mx, lg[k]);
        float e[KS], se = 0.f;
#pragma unroll
        for (int k = 0; k < KS; k++) { e[k] = __expf(lg[k] - mx); se += e[k]; }
        float inv = 1.f / se;
#pragma unroll
        for (int k = 0; k < KS; k++) {
            float a = e[k] * inv;
            sacc[k] += a;
            if (l == (unsigned)k) as_[k][nl] = a;
        }
    }
    __syncthreads();
#pragma unroll
    for (int k = 0; k < KS; k++)
        attn_out[((long)(b * KS + k)) * NTOK + n0 + t] = as_[k][t];
    if (l == 0)
#pragma unroll
        for (int k = 0; k < KS; k++) atomicAdd(&d_msum[b * KS + k], sacc[k]);
}

// ---------------- kernel 8: per-batch GRU + LN + MLP slot update -----------
__global__ __launch_bounds__(256) void slot_upd_all(
    const float* __restrict__ W_ih, const float* __restrict__ W_hh,
    const float* __restrict__ b_ih, const float* __restrict__ b_hh,
    const float* __restrict__ g_m, const float* __restrict__ b_m,
    const float* __restrict__ W1, const float* __restrict__ b1,
    const float* __restrict__ W2, const float* __restrict__ b2) {
    int b = blockIdx.x;
    int t = threadIdx.x, w = t >> 5, l = t & 31;
    __shared__ float u[KS][DS];    // updates, then reused as h
    __shared__ float so[KS][DS];
    __shared__ float hn[KS][DS];
    __shared__ float m1[KS][DS];
    __shared__ float mrs[KS][2];

#pragma unroll
    for (int k = 0; k < KS; k++) {
        float Sv = d_S[b * KS + k] + EPSV;
        u[k][t]  = d_U[(b * KS + k) * DS + t] / Sv;
        so[k][t] = d_slots[(b * KS + k) * DS + t];
    }
    __syncthreads();

    float gi[3][KS], gh[3][KS];
#pragma unroll
    for (int g = 0; g < 3; g++)
#pragma unroll
        for (int k = 0; k < KS; k++) { gi[g][k] = 0.f; gh[g][k] = 0.f; }

    const float4* wi0 = (const float4*)(W_ih + (long)t * DS);
    const float4* wi1 = (const float4*)(W_ih + (long)(DS + t) * DS);
    const float4* wi2 = (const float4*)(W_ih + (long)(2 * DS + t) * DS);
    const float4* wh0 = (const float4*)(W_hh + (long)t * DS);
    const float4* wh1 = (const float4*)(W_hh + (long)(DS + t) * DS);
    const float4* wh2 = (const float4*)(W_hh + (long)(2 * DS + t) * DS);
    for (int d4 = 0; d4 < 64; d4++) {
        float4 a0 = wi0[d4], a1 = wi1[d4], a2 = wi2[d4];
        float4 c0 = wh0[d4], c1 = wh1[d4], c2 = wh2[d4];
#pragma unroll
        for (int k = 0; k < KS; k++) {
            float4 uv = *(const float4*)&u[k][d4 * 4];
            float4 sv = *(const float4*)&so[k][d4 * 4];
            gi[0][k] += a0.x * uv.x + a0.y * uv.y + a0.z * uv.z + a0.w * uv.w;
            gi[1][k] += a1.x * uv.x + a1.y * uv.y + a1.z * uv.z + a1.w * uv.w;
            gi[2][k] += a2.x * uv.x + a2.y * uv.y + a2.z * uv.z + a2.w * uv.w;
            gh[0][k] += c0.x * sv.x + c0.y * sv.y + c0.z * sv.z + c0.w * sv.w;
            gh[1][k] += c1.x * sv.x + c1.y * sv.y + c1.z * sv.z + c1.w * sv.w;
            gh[2][k] += c2.x * sv.x + c2.y * sv.y + c2.z * sv.z + c2.w * sv.w;
        }
    }
    float bi0 = b_ih[t], bi1 = b_ih[DS + t], bi2 = b_ih[2 * DS + t];
    float bh0 = b_hh[t], bh1 = b_hh[DS + t], bh2 = b_hh[2 * DS + t];
    __syncthreads();
#pragma unroll
    for (int k = 0; k < KS; k++) {
        float r  = 1.f / (1.f + __expf(-(gi[0][k] + bi0 + gh[0][k] + bh0)));
        float z  = 1.f / (1.f + __expf(-(gi[1][k] + bi1 + gh[1][k] + bh1)));
        float nn = tanhf(gi[2][k] + bi2 + r * (gh[2][k] + bh2));
        u[k][t] = (1.f - z) * nn + z * so[k][t];   // h
    }
    __syncthreads();

    {
        float s = 0.f, s2 = 0.f;
#pragma unroll
        for (int j = 0; j < 8; j++) {
            float v = u[w][l + 32 * j];
            s += v; s2 += v * v;
        }
#pragma unroll
        for (int o = 16; o; o >>= 1) {
            s  += __shfl_xor_sync(~0u, s, o);
            s2 += __shfl_xor_sync(~0u, s2, o);
        }
        if (l == 0) {
            float m = s * (1.f / DS);
            float var = s2 * (1.f / DS) - m * m;
            mrs[w][0] = m;
            mrs[w][1] = rsqrtf(var + LNEPS);
        }
    }
    __syncthreads();
    float gmt = g_m[t], bmt = b_m[t];
#pragma unroll
    for (int k = 0; k < KS; k++)
        hn[k][t] = (u[k][t] - mrs[k][0]) * mrs[k][1] * gmt + bmt;
    __syncthreads();

    {
        float a1[KS];
#pragma unroll
        for (int k = 0; k < KS; k++) a1[k] = 0.f;
        const float4* w14 = (const float4*)(W1 + (long)t * DS);
        for (int d4 = 0; d4 < 64; d4++) {
            float4 wv = w14[d4];
#pragma unroll
            for (int k = 0; k < KS; k++) {
                float4 hv = *(const float4*)&hn[k][d4 * 4];
                a1[k] += wv.x * hv.x + wv.y * hv.y + wv.z * hv.z + wv.w * hv.w;
            }
        }
        float b1t = b1[t];
#pragma unroll
        for (int k = 0; k < KS; k++) m1[k][t] = fmaxf(a1[k] + b1t, 0.f);
    }
    __syncthreads();
    {
        float a2[KS];
#pragma unroll
        for (int k = 0; k < KS; k++) a2[k] = 0.f;
        const float4* w24 = (const float4*)(W2 + (long)t * DS);
        for (int d4 = 0; d4 < 64; d4++) {
            float4 wv = w24[d4];
#pragma unroll
            for (int k = 0; k < KS; k++) {
                float4 mv = *(const float4*)&m1[k][d4 * 4];
                a2[k] += wv.x * mv.x + wv.y * mv.y + wv.z * mv.z + wv.w * mv.w;
            }
        }
        float b2t = b2[t];
#pragma unroll
        for (int k = 0; k < KS; k++)
            d_slots[(b * KS + k) * DS + t] = u[k][t] + a2[k] + b2t;
    }
}

// ---------------- kernel 9: confidence blend -------------------------------
__global__ void blend(const float* __restrict__ prev, float* __restrict__ out) {
    int i = blockIdx.x * 256 + threadIdx.x;
    int bk = i >> 8;
    float mask = 1.f / (1.f + __expf(-d_msum[bk] * (1.f / NTOK)));
    out[i] = d_slots[i] * mask + prev[i] * (1.f - mask);
}

// ---------------- launch ---------------------------------------------------
extern "C" void kernel_launch(void* const* d_in, const int* in_sizes, int n_in,
                              void* d_out, int out_size) {
    const float* features  = (const float*)d_in[0];
    const float* prev      = (const float*)d_in[1];
    const float* g_in      = (const float*)d_in[2];
    const float* b_in      = (const float*)d_in[3];
    const float* g_s       = (const float*)d_in[4];
    const float* b_s       = (const float*)d_in[5];
    const float* g_m       = (const float*)d_in[6];
    const float* b_m       = (const float*)d_in[7];
    const float* Wq        = (const float*)d_in[8];
    const float* Wk        = (const float*)d_in[9];
    const float* Wv        = (const float*)d_in[10];
    const float* W_ih      = (const float*)d_in[11];
    const float* W_hh      = (const float*)d_in[12];
    const float* b_ih      = (const float*)d_in[13];
    const float* b_hh      = (const float*)d_in[14];
    const float* W1        = (const float*)d_in[15];
    const float* b1        = (const float*)d_in[16];
    const float* W2        = (const float*)d_in[17];
    const float* b2        = (const float*)d_in[18];

    float* out      = (float*)d_out;
    float* attn_out = out + B * KS * DS;

    cudaFuncSetAttribute(kv_gemm_mma, cudaFuncAttributeMaxDynamicSharedMemorySize, SMEM_GEMM);

    prep_weights<<<DH + DS, 256>>>(Wk, Wv, g_in, b_in);
    row_stats<<<B * NTOK / 8, 256>>>(features);
    kv_gemm_mma<<<dim3(4, B * NTOK / 128), 256, SMEM_GEMM>>>(features);
    copy_slots<<<B * KS * DS / 256, 256>>>(prev);

    for (int it = 0; it < NITER; it++) {
        slot_q_all<<<B, 256>>>(g_s, b_s, Wq);
        attn_iter<<<dim3(NTOK / 256, B), 256>>>();
        slot_upd_all<<<B, 256>>>(W_ih, W_hh, b_ih, b_hh, g_m, b_m, W1, b1, W2, b2);
    }
    slot_q_all<<<B, 256>>>(g_s, b_s, Wq);
    attn_final<<<dim3(NTOK / 256, B), 256>>>(attn_out);
    blend<<<B * KS * DS / 256, 256>>>(prev, out);
}